// round 3
// baseline (speedup 1.0000x reference)
#include <cuda_runtime.h>
#include <cstdint>
#include <cstddef>

namespace {

constexpr int D_    = 256;   // embedding dim
constexpr int SLEN  = 512;   // sequence length (fixed for this problem)
constexpr int TPG   = 8;     // tokens per block-iteration
constexpr int PAD_ID = 72;   // VOCAB
constexpr int NBLOCKS = 296; // grid-stride persistent-ish grid (2 CTAs/SM target)

// Block-wide mean/rstd of one value per thread (256 threads).
__device__ __forceinline__ void block_stats(float hh, float* s_red, float* s_ms,
                                            int tid, int lane, int wid,
                                            float& mu, float& rs)
{
    __syncthreads();  // protect s_red/s_ms from any prior use
    float s1 = hh, s2 = hh * hh;
#pragma unroll
    for (int o = 16; o; o >>= 1) {
        s1 += __shfl_xor_sync(0xffffffffu, s1, o);
        s2 += __shfl_xor_sync(0xffffffffu, s2, o);
    }
    if (lane == 0) { s_red[wid * 2] = s1; s_red[wid * 2 + 1] = s2; }
    __syncthreads();
    if (tid == 0) {
        float t1 = 0.f, t2 = 0.f;
#pragma unroll
        for (int w = 0; w < 8; ++w) { t1 += s_red[w * 2]; t2 += s_red[w * 2 + 1]; }
        float m = t1 * (1.f / 256.f);
        float v = t2 * (1.f / 256.f) - m * m;
        s_ms[0] = m;
        s_ms[1] = rsqrtf(v + 1e-5f);
    }
    __syncthreads();
    mu = s_ms[0];
    rs = s_ms[1];
}

__global__ __launch_bounds__(256, 2) void poker_fused_kernel(
    const int*   __restrict__ token_ids,
    const int*   __restrict__ token_streets,
    const int*   __restrict__ card_ranks,
    const int*   __restrict__ card_suits,
    const int*   __restrict__ action_actors,
    const float* __restrict__ legal_masks,   // [T,16]
    const float* __restrict__ cf,            // [T,9] context_features
    const float* __restrict__ base_emb,      // [73,256]
    const float* __restrict__ street_emb,    // [4,256]
    const float* __restrict__ rank_emb,      // [13,256]
    const float* __restrict__ suit_emb,      // [4,256]
    const float* __restrict__ actor_emb,     // [2,256]
    const float* __restrict__ atype_emb,     // [16,256]
    const float* __restrict__ legal_W,       // [256,16]
    const float* __restrict__ legal_b,
    const float* __restrict__ legal_g,
    const float* __restrict__ legal_be,
    const float* __restrict__ game_W,        // [256,5]
    const float* __restrict__ game_b,
    const float* __restrict__ game_g,
    const float* __restrict__ game_be,
    const float* __restrict__ ctx_W,         // [256,143]
    const float* __restrict__ ctx_b,
    const float* __restrict__ ctx_g,
    const float* __restrict__ ctx_be,
    float*       __restrict__ out,           // [T,256]
    int n_groups)
{
    __shared__ int    s_id[TPG], s_st[TPG], s_rk[TPG], s_su[TPG], s_ac[TPG], s_fl[TPG];
    __shared__ float4 s_x4[TPG][4];     // legal-mask vectors, 16 floats/token
    __shared__ float  s_red[128];       // reduction scratch (8 warps x 8 tok x 2)
    __shared__ float  s_ms[16];         // per-token (mu, rstd)
    __shared__ float  s_p[13];
    __shared__ float  s_ca[144];        // ctx_all (143, padded)

    const int tid  = threadIdx.x;      // == dimension d owned by this thread
    const int lane = tid & 31;
    const int wid  = tid >> 5;

    // ---- per-dim weights, loaded ONCE per block lifetime (register-resident) ----
    float lw[16];
    {
        const float4* wq = reinterpret_cast<const float4*>(legal_W) + tid * 4;
        float4 q0 = wq[0], q1 = wq[1], q2 = wq[2], q3 = wq[3];
        lw[0] = q0.x; lw[1] = q0.y; lw[2]  = q0.z; lw[3]  = q0.w;
        lw[4] = q1.x; lw[5] = q1.y; lw[6]  = q1.z; lw[7]  = q1.w;
        lw[8] = q2.x; lw[9] = q2.y; lw[10] = q2.z; lw[11] = q2.w;
        lw[12]= q3.x; lw[13]= q3.y; lw[14] = q3.z; lw[15] = q3.w;
    }
    float gw[5];
#pragma unroll
    for (int k = 0; k < 5; ++k) gw[k] = game_W[tid * 5 + k];
    const float lb  = legal_b[tid], lg = legal_g[tid], lbt = legal_be[tid];
    const float gb  = game_b[tid],  gg = game_g[tid],  gbt = game_be[tid];
    const float cb  = ctx_b[tid],   cg = ctx_g[tid],   cbt = ctx_be[tid];

    for (int grp = blockIdx.x; grp < n_groups; grp += gridDim.x) {
        const int t0 = grp * TPG;
        __syncthreads();  // smem reuse barrier between iterations

        if (tid < TPG) {
            const int t = t0 + tid;
            int raw = token_ids[t];
            int pad = (raw < 0) ? 1 : 0;
            int id  = pad ? PAD_ID : raw;
            s_id[tid] = id;
            s_st[tid] = token_streets[t];
            int rk = card_ranks[t];    rk = rk < 0 ? 0 : (rk > 12 ? 12 : rk);
            int su = card_suits[t];    su = su < 0 ? 0 : (su > 3  ? 3  : su);
            int ac = action_actors[t]; ac = ac < 0 ? 0 : (ac > 1  ? 1  : ac);
            s_rk[tid] = rk; s_su[tid] = su; s_ac[tid] = ac;
            int f = pad;
            if (id >= 4  && id < 56) f |= 2;   // card
            if (id >= 56 && id < 72) f |= 4;   // action
            if (id == 1)             f |= 8;   // ctx
            s_fl[tid] = f;
        }
        if (tid < TPG * 16) {
            reinterpret_cast<float*>(s_x4)[tid] = legal_masks[(size_t)t0 * 16 + tid];
        }
        __syncthreads();

        int fl[TPG];
#pragma unroll
        for (int i = 0; i < TPG; ++i) fl[i] = s_fl[i];
        int anyAct = 0, anyCtx = 0;
#pragma unroll
        for (int i = 0; i < TPG; ++i) { anyAct |= (fl[i] & 4); anyCtx |= (fl[i] & 8); }

        float acc[TPG];
        float h[TPG];
#pragma unroll
        for (int i = 0; i < TPG; ++i) h[i] = 0.f;

        // ---- phase A: embedding sums + legal-MLP linear (pre-LN) ----
#pragma unroll
        for (int i = 0; i < TPG; ++i) {
            const int id = s_id[i];
            float a = __ldg(base_emb + id * D_ + tid) + __ldg(street_emb + s_st[i] * D_ + tid);
            if (fl[i] & 2)
                a += __ldg(rank_emb + s_rk[i] * D_ + tid) + __ldg(suit_emb + s_su[i] * D_ + tid);
            if (fl[i] & 4) {
                a += __ldg(actor_emb + s_ac[i] * D_ + tid) + __ldg(atype_emb + (id - 56) * D_ + tid);
                const float4 x0 = s_x4[i][0], x1 = s_x4[i][1], x2 = s_x4[i][2], x3 = s_x4[i][3];
                float pa = lb, pb = 0.f;
                pa = fmaf(lw[0],  x0.x, pa); pb = fmaf(lw[1],  x0.y, pb);
                pa = fmaf(lw[2],  x0.z, pa); pb = fmaf(lw[3],  x0.w, pb);
                pa = fmaf(lw[4],  x1.x, pa); pb = fmaf(lw[5],  x1.y, pb);
                pa = fmaf(lw[6],  x1.z, pa); pb = fmaf(lw[7],  x1.w, pb);
                pa = fmaf(lw[8],  x2.x, pa); pb = fmaf(lw[9],  x2.y, pb);
                pa = fmaf(lw[10], x2.z, pa); pb = fmaf(lw[11], x2.w, pb);
                pa = fmaf(lw[12], x3.x, pa); pb = fmaf(lw[13], x3.y, pb);
                pa = fmaf(lw[14], x3.z, pa); pb = fmaf(lw[15], x3.w, pb);
                h[i] = pa + pb;
            }
            acc[i] = a;
        }

        // ---- legal LayerNorm + ReLU, batched over all action tokens ----
        if (anyAct) {
#pragma unroll
            for (int i = 0; i < TPG; ++i) {
                if (fl[i] & 4) {
                    float s1 = h[i], s2 = h[i] * h[i];
#pragma unroll
                    for (int o = 16; o; o >>= 1) {
                        s1 += __shfl_xor_sync(0xffffffffu, s1, o);
                        s2 += __shfl_xor_sync(0xffffffffu, s2, o);
                    }
                    if (lane == 0) {
                        s_red[wid * 16 + i * 2]     = s1;
                        s_red[wid * 16 + i * 2 + 1] = s2;
                    }
                }
            }
            __syncthreads();
            if (tid < TPG && (s_fl[tid] & 4)) {
                float t1 = 0.f, t2 = 0.f;
#pragma unroll
                for (int w = 0; w < 8; ++w) {
                    t1 += s_red[w * 16 + tid * 2];
                    t2 += s_red[w * 16 + tid * 2 + 1];
                }
                const float mu  = t1 * (1.f / 256.f);
                const float var = t2 * (1.f / 256.f) - mu * mu;
                s_ms[tid * 2]     = mu;
                s_ms[tid * 2 + 1] = rsqrtf(var + 1e-5f);
            }
            __syncthreads();
#pragma unroll
            for (int i = 0; i < TPG; ++i) {
                if (fl[i] & 4) {
                    float v = (h[i] - s_ms[i * 2]) * s_ms[i * 2 + 1] * lg + lbt;
                    acc[i] += fmaxf(v, 0.f);
                }
            }
        }

        // ---- game MLP: only at sequence position 0 (token i==0 when t0%512==0) ----
        if ((t0 & (SLEN - 1)) == 0) {
            const int n = t0 >> 9;
            const float* c0 = cf + (size_t)n * SLEN * 9;
            const float sb = __ldg(c0 + 0), bb = __ldg(c0 + 1), po = __ldg(c0 + 2);
            const float scale = 100.f * bb;
            const float ssg = (scale == 0.f) ? 1e-8f : scale;
            float hh = gb;
            hh = fmaf(gw[0], sb, hh);
            hh = fmaf(gw[1], bb, hh);
            hh = fmaf(gw[2], po, hh);
            hh = fmaf(gw[3], bb / ssg, hh);
            hh = fmaf(gw[4], sb / ssg, hh);
            float mu, rs;
            block_stats(hh, s_red, s_ms, tid, lane, wid, mu, rs);
            float v = (hh - mu) * rs * gg + gbt;
            acc[0] += fmaxf(v, 0.f);
        }

        // ---- ctx MLP (rare): warp-cooperative coalesced dot over 143 inputs ----
        if (anyCtx) {
#pragma unroll 1
            for (int i = 0; i < TPG; ++i) {
                if (!(fl[i] & 8)) continue;   // uniform across block
                const int t = t0 + i;
                const int n = t >> 9;
                __syncthreads();
                if (tid < 13) {
                    const float* c0 = cf + (size_t)n * SLEN * 9;
                    const float* cp = cf + (size_t)t * 9;
                    const float bb = __ldg(c0 + 1);
                    const float scale = 100.f * bb;
                    const float ssafe   = (scale == 0.f) ? 1.f : scale;
                    const float bbsafe  = (bb == 0.f) ? 1.f : bb;
                    const float pot     = __ldg(cp + 0);
                    const float potsafe = (pot == 0.f) ? 1.f : pot;
                    float num, den;
                    switch (tid) {
                        case 0:  num = pot;            den = ssafe;   break;
                        case 1:  num = __ldg(cp + 1);  den = ssafe;   break;
                        case 2:  num = __ldg(cp + 2);  den = ssafe;   break;
                        case 3:  num = __ldg(cp + 3);  den = ssafe;   break;
                        case 4:  num = __ldg(cp + 4);  den = ssafe;   break;
                        case 5:  num = __ldg(cp + 5);  den = 1.f;     break;
                        case 6:  num = __ldg(cp + 6);  den = 1.f;     break;
                        case 7:  num = __ldg(cp + 7);  den = ssafe;   break;
                        case 8:  num = __ldg(cp + 8);  den = ssafe;   break;
                        case 9:  num = __ldg(cp + 1);  den = bbsafe;  break;
                        case 10: num = __ldg(cp + 2);  den = bbsafe;  break;
                        case 11: num = __ldg(cp + 1);  den = potsafe; break;
                        default: num = __ldg(cp + 2);  den = potsafe; break;
                    }
                    s_p[tid] = num / den;
                }
                __syncthreads();
                if (tid < 143) {
                    const int fi = tid / 11;
                    const int ps = tid - fi * 11;
                    const float pv = s_p[fi];
                    float val;
                    if (ps == 0)      val = pv;
                    else if (ps <= 5) val = sinpif(pv * (float)(1 << (ps - 1)));
                    else              val = cospif(pv * (float)(1 << (ps - 6)));
                    s_ca[tid] = val;
                }
                __syncthreads();
                float hc = 0.f;
                {
                    const int dbase = wid * 32;
                    const float ca0 = s_ca[lane];
                    const float ca1 = s_ca[lane + 32];
                    const float ca2 = s_ca[lane + 64];
                    const float ca3 = s_ca[lane + 96];
                    const float ca4 = (lane < 15) ? s_ca[lane + 128] : 0.f;
                    for (int dd = 0; dd < 32; ++dd) {
                        const float* wr = ctx_W + (size_t)(dbase + dd) * 143;
                        float sum = ca0 * __ldg(wr + lane)
                                  + ca1 * __ldg(wr + lane + 32)
                                  + ca2 * __ldg(wr + lane + 64)
                                  + ca3 * __ldg(wr + lane + 96);
                        if (lane < 15) sum += ca4 * __ldg(wr + lane + 128);
#pragma unroll
                        for (int o = 16; o; o >>= 1)
                            sum += __shfl_xor_sync(0xffffffffu, sum, o);
                        if (dd == lane) hc = sum;   // lane dd owns dim dbase+dd == its tid
                    }
                }
                hc += cb;
                float mu, rs;
                block_stats(hc, s_red, s_ms, tid, lane, wid, mu, rs);
                float v = (hc - mu) * rs * cg + cbt;
                acc[i] += fmaxf(v, 0.f);
            }
        }

        // ---- store (pad -> 0), coalesced ----
        float* op = out + (size_t)t0 * D_ + tid;
#pragma unroll
        for (int i = 0; i < TPG; ++i) {
            op[(size_t)i * D_] = (fl[i] & 1) ? 0.f : acc[i];
        }
    }
}

} // namespace

extern "C" void kernel_launch(void* const* d_in, const int* in_sizes, int n_in,
                              void* d_out, int out_size)
{
    const int tokens   = in_sizes[0];       // N*S
    const int n_groups = tokens / TPG;

    poker_fused_kernel<<<NBLOCKS, 256>>>(
        (const int*)  d_in[0],   // token_ids
        (const int*)  d_in[1],   // token_streets
        (const int*)  d_in[2],   // card_ranks
        (const int*)  d_in[3],   // card_suits
        (const int*)  d_in[4],   // action_actors
        (const float*)d_in[5],   // action_legal_masks
        (const float*)d_in[6],   // context_features
        (const float*)d_in[7],   // base_emb
        (const float*)d_in[8],   // street_emb
        (const float*)d_in[9],   // rank_emb
        (const float*)d_in[10],  // suit_emb
        (const float*)d_in[11],  // actor_emb
        (const float*)d_in[12],  // atype_emb
        (const float*)d_in[13],  // legal_W
        (const float*)d_in[14],  // legal_b
        (const float*)d_in[15],  // legal_g
        (const float*)d_in[16],  // legal_beta
        (const float*)d_in[17],  // game_W
        (const float*)d_in[18],  // game_b
        (const float*)d_in[19],  // game_g
        (const float*)d_in[20],  // game_beta
        (const float*)d_in[21],  // ctx_W
        (const float*)d_in[22],  // ctx_b
        (const float*)d_in[23],  // ctx_g
        (const float*)d_in[24],  // ctx_beta
        (float*)d_out,
        n_groups);
}

// round 4
// speedup vs baseline: 2.1659x; 2.1659x over previous
#include <cuda_runtime.h>
#include <cstdint>
#include <cstddef>

namespace {

constexpr int PAD_ID  = 72;    // VOCAB
constexpr int NBLOCKS = 444;   // 3 CTAs/SM * 148 SMs, one wave

// warp LayerNorm stats over 256 values (8 per lane)
__device__ __forceinline__ void warp_ln(const float* h, float& mu, float& rs)
{
    float s1 = 0.f, s2 = 0.f;
#pragma unroll
    for (int k = 0; k < 8; ++k) { s1 += h[k]; s2 = fmaf(h[k], h[k], s2); }
#pragma unroll
    for (int o = 16; o; o >>= 1) {
        s1 += __shfl_xor_sync(0xffffffffu, s1, o);
        s2 += __shfl_xor_sync(0xffffffffu, s2, o);
    }
    mu = s1 * (1.f / 256.f);
    float var = s2 * (1.f / 256.f) - mu * mu;
    rs = rsqrtf(var + 1e-5f);
}

__global__ __launch_bounds__(256, 3) void poker_warp_kernel(
    const int*   __restrict__ token_ids,
    const int*   __restrict__ token_streets,
    const int*   __restrict__ card_ranks,
    const int*   __restrict__ card_suits,
    const int*   __restrict__ action_actors,
    const float* __restrict__ legal_masks,   // [T,16]
    const float* __restrict__ cf,            // [T,9]
    const float* __restrict__ base_emb,      // [73,256]
    const float* __restrict__ street_emb,    // [4,256]
    const float* __restrict__ rank_emb,      // [13,256]
    const float* __restrict__ suit_emb,      // [4,256]
    const float* __restrict__ actor_emb,     // [2,256]
    const float* __restrict__ atype_emb,     // [16,256]
    const float* __restrict__ legal_W,       // [256,16]
    const float* __restrict__ legal_b,
    const float* __restrict__ legal_g,
    const float* __restrict__ legal_be,
    const float* __restrict__ game_W,        // [256,5]
    const float* __restrict__ game_b,
    const float* __restrict__ game_g,
    const float* __restrict__ game_be,
    const float* __restrict__ ctx_W,         // [256,143]
    const float* __restrict__ ctx_b,
    const float* __restrict__ ctx_g,
    const float* __restrict__ ctx_be,
    float*       __restrict__ out,           // [T,256]
    int tokens)
{
    __shared__ float4 s_W[1024];        // swizzled legal_W (16 KB)
    __shared__ float  s_ca[8][160];     // per-warp ctx scratch (padded, 5 KB)

    const int tid  = threadIdx.x;
    const int lane = tid & 31;
    const int wid  = tid >> 5;

    // ---- stage legal_W into smem, XOR-swizzled so per-dim LDS.128 is conflict-free ----
    {
        const float4* Wg = reinterpret_cast<const float4*>(legal_W);
        for (int q = tid; q < 1024; q += 256)
            s_W[q ^ ((q >> 5) & 7)] = Wg[q];
    }
    __syncthreads();   // the ONLY block barrier

    const int gwarp = blockIdx.x * 8 + wid;
    const int nwarp = gridDim.x * 8;
    const int l8    = lane << 3;        // first dim owned by this lane
    const int swbase = (lane << 5);     // s_W row base
    const int swxor  = lane & 7;

    for (int t = gwarp; t < tokens; t += nwarp) {
        const int  raw = __ldg(token_ids + t);
        const bool pad = raw < 0;
        const int  id  = pad ? PAD_ID : raw;
        const int  st  = __ldg(token_streets + t);

        float ar[8];
        {
            const float4* bp = reinterpret_cast<const float4*>(base_emb)   + id * 64 + lane * 2;
            const float4* sp = reinterpret_cast<const float4*>(street_emb) + st * 64 + lane * 2;
            const float4 b0 = __ldg(bp), b1 = __ldg(bp + 1);
            const float4 s0 = __ldg(sp), s1 = __ldg(sp + 1);
            ar[0] = b0.x + s0.x; ar[1] = b0.y + s0.y; ar[2] = b0.z + s0.z; ar[3] = b0.w + s0.w;
            ar[4] = b1.x + s1.x; ar[5] = b1.y + s1.y; ar[6] = b1.z + s1.z; ar[7] = b1.w + s1.w;
        }

        if (id >= 4 && id < 56) {
            // ---- card token (warp-uniform branch) ----
            int rk = __ldg(card_ranks + t); rk = rk < 0 ? 0 : (rk > 12 ? 12 : rk);
            int su = __ldg(card_suits + t); su = su < 0 ? 0 : (su > 3  ? 3  : su);
            const float4* rp = reinterpret_cast<const float4*>(rank_emb) + rk * 64 + lane * 2;
            const float4* up = reinterpret_cast<const float4*>(suit_emb) + su * 64 + lane * 2;
            const float4 r0 = __ldg(rp), r1 = __ldg(rp + 1);
            const float4 u0 = __ldg(up), u1 = __ldg(up + 1);
            ar[0] += r0.x + u0.x; ar[1] += r0.y + u0.y; ar[2] += r0.z + u0.z; ar[3] += r0.w + u0.w;
            ar[4] += r1.x + u1.x; ar[5] += r1.y + u1.y; ar[6] += r1.z + u1.z; ar[7] += r1.w + u1.w;
        } else if (id >= 56 && id < 72) {
            // ---- action token ----
            int ac = __ldg(action_actors + t); ac = ac < 0 ? 0 : (ac > 1 ? 1 : ac);
            const float4* ap = reinterpret_cast<const float4*>(actor_emb) + ac * 64 + lane * 2;
            const float4* tp = reinterpret_cast<const float4*>(atype_emb) + (id - 56) * 64 + lane * 2;
            const float4 a0 = __ldg(ap), a1 = __ldg(ap + 1);
            const float4 y0 = __ldg(tp), y1 = __ldg(tp + 1);
            ar[0] += a0.x + y0.x; ar[1] += a0.y + y0.y; ar[2] += a0.z + y0.z; ar[3] += a0.w + y0.w;
            ar[4] += a1.x + y1.x; ar[5] += a1.y + y1.y; ar[6] += a1.z + y1.z; ar[7] += a1.w + y1.w;

            // x (16 floats, broadcast across lanes)
            float xv[16];
            {
                const float4* xp = reinterpret_cast<const float4*>(legal_masks) + (size_t)t * 4;
                const float4 x0 = __ldg(xp), x1 = __ldg(xp + 1), x2 = __ldg(xp + 2), x3 = __ldg(xp + 3);
                xv[0]=x0.x; xv[1]=x0.y; xv[2]=x0.z; xv[3]=x0.w;
                xv[4]=x1.x; xv[5]=x1.y; xv[6]=x1.z; xv[7]=x1.w;
                xv[8]=x2.x; xv[9]=x2.y; xv[10]=x2.z; xv[11]=x2.w;
                xv[12]=x3.x; xv[13]=x3.y; xv[14]=x3.z; xv[15]=x3.w;
            }
            float h[8];
            {
                const float4* bbp = reinterpret_cast<const float4*>(legal_b) + lane * 2;
                const float4 hb0 = __ldg(bbp), hb1 = __ldg(bbp + 1);
                h[0]=hb0.x; h[1]=hb0.y; h[2]=hb0.z; h[3]=hb0.w;
                h[4]=hb1.x; h[5]=hb1.y; h[6]=hb1.z; h[7]=hb1.w;
            }
#pragma unroll
            for (int kk = 0; kk < 8; ++kk) {
#pragma unroll
                for (int j = 0; j < 4; ++j) {
                    const float4 w = s_W[swbase + (((kk << 2) | j) ^ swxor)];
                    h[kk] = fmaf(w.x, xv[4*j + 0], h[kk]);
                    h[kk] = fmaf(w.y, xv[4*j + 1], h[kk]);
                    h[kk] = fmaf(w.z, xv[4*j + 2], h[kk]);
                    h[kk] = fmaf(w.w, xv[4*j + 3], h[kk]);
                }
            }
            float mu, rs;
            warp_ln(h, mu, rs);
            const float4* gp = reinterpret_cast<const float4*>(legal_g)  + lane * 2;
            const float4* ep = reinterpret_cast<const float4*>(legal_be) + lane * 2;
            const float4 g0 = __ldg(gp), g1 = __ldg(gp + 1);
            const float4 e0 = __ldg(ep), e1 = __ldg(ep + 1);
            const float gg[8] = {g0.x,g0.y,g0.z,g0.w,g1.x,g1.y,g1.z,g1.w};
            const float ee[8] = {e0.x,e0.y,e0.z,e0.w,e1.x,e1.y,e1.z,e1.w};
#pragma unroll
            for (int kk = 0; kk < 8; ++kk) {
                const float v = fmaf((h[kk] - mu) * rs, gg[kk], ee[kk]);
                ar[kk] += fmaxf(v, 0.f);
            }
        }

        // ---- game MLP: sequence position 0 only (256 occurrences total) ----
        if ((t & 511) == 0) {
            const int n = t >> 9;
            const float* c0 = cf + (size_t)n * 512 * 9;
            const float sb = __ldg(c0), bb = __ldg(c0 + 1), po = __ldg(c0 + 2);
            const float scale = 100.f * bb;
            const float ssg = (scale == 0.f) ? 1e-8f : scale;
            const float f3 = bb / ssg, f4 = sb / ssg;
            float h[8];
            {
                const float4* bbp = reinterpret_cast<const float4*>(game_b) + lane * 2;
                const float4 hb0 = __ldg(bbp), hb1 = __ldg(bbp + 1);
                h[0]=hb0.x; h[1]=hb0.y; h[2]=hb0.z; h[3]=hb0.w;
                h[4]=hb1.x; h[5]=hb1.y; h[6]=hb1.z; h[7]=hb1.w;
            }
#pragma unroll
            for (int kk = 0; kk < 8; ++kk) {
                const float* wr = game_W + (size_t)(l8 + kk) * 5;
                float s = h[kk];
                s = fmaf(__ldg(wr + 0), sb, s);
                s = fmaf(__ldg(wr + 1), bb, s);
                s = fmaf(__ldg(wr + 2), po, s);
                s = fmaf(__ldg(wr + 3), f3, s);
                s = fmaf(__ldg(wr + 4), f4, s);
                h[kk] = s;
            }
            float mu, rs;
            warp_ln(h, mu, rs);
            const float4* gp = reinterpret_cast<const float4*>(game_g)  + lane * 2;
            const float4* ep = reinterpret_cast<const float4*>(game_be) + lane * 2;
            const float4 g0 = __ldg(gp), g1 = __ldg(gp + 1);
            const float4 e0 = __ldg(ep), e1 = __ldg(ep + 1);
            const float gg[8] = {g0.x,g0.y,g0.z,g0.w,g1.x,g1.y,g1.z,g1.w};
            const float ee[8] = {e0.x,e0.y,e0.z,e0.w,e1.x,e1.y,e1.z,e1.w};
#pragma unroll
            for (int kk = 0; kk < 8; ++kk) {
                const float v = fmaf((h[kk] - mu) * rs, gg[kk], ee[kk]);
                ar[kk] += fmaxf(v, 0.f);
            }
        }

        // ---- ctx MLP (id == 1, ~1.4% of tokens) ----
        if (id == 1) {
            const int n = t >> 9;
            const float* c0 = cf + (size_t)n * 512 * 9;
            const float* cp = cf + (size_t)t * 9;
            float pv = 0.f;
            if (lane < 13) {
                const float bb = __ldg(c0 + 1);
                const float scale = 100.f * bb;
                const float ssafe   = (scale == 0.f) ? 1.f : scale;
                const float bbsafe  = (bb == 0.f) ? 1.f : bb;
                const float pot     = __ldg(cp);
                const float potsafe = (pot == 0.f) ? 1.f : pot;
                const int si = (lane < 9) ? lane : ((lane < 11) ? lane - 8 : lane - 10);
                const float num = __ldg(cp + si);
                float den = ssafe;
                if (lane == 5 || lane == 6)       den = 1.f;
                else if (lane == 9 || lane == 10) den = bbsafe;
                else if (lane >= 11)              den = potsafe;
                pv = num / den;
            }
            float* ca = s_ca[wid];
#pragma unroll
            for (int m = 0; m < 5; ++m) {
                const int idx = lane + 32 * m;
                int fi = idx / 11;
                if (fi > 12) fi = 12;
                const int ps = idx - fi * 11;
                const float p = __shfl_sync(0xffffffffu, pv, fi);
                float val;
                if (ps == 0)      val = p;
                else if (ps <= 5) val = sinpif(p * (float)(1 << (ps - 1)));
                else              val = cospif(p * (float)(1 << (ps - 6)));
                ca[idx] = (idx < 143) ? val : 0.f;
            }
            __syncwarp();

            float h[8];
            {
                const float4* bbp = reinterpret_cast<const float4*>(ctx_b) + lane * 2;
                const float4 hb0 = __ldg(bbp), hb1 = __ldg(bbp + 1);
                h[0]=hb0.x; h[1]=hb0.y; h[2]=hb0.z; h[3]=hb0.w;
                h[4]=hb1.x; h[5]=hb1.y; h[6]=hb1.z; h[7]=hb1.w;
            }
            const float ca0 = ca[lane];
            const float ca1 = ca[lane + 32];
            const float ca2 = ca[lane + 64];
            const float ca3 = ca[lane + 96];
            const float ca4 = (lane < 15) ? ca[lane + 128] : 0.f;
#pragma unroll 1
            for (int c = 0; c < 32; ++c) {
#pragma unroll
                for (int kk = 0; kk < 8; ++kk) {
                    const float* wr = ctx_W + (size_t)(c * 8 + kk) * 143;
                    float sum = ca0 * __ldg(wr + lane)
                              + ca1 * __ldg(wr + lane + 32)
                              + ca2 * __ldg(wr + lane + 64)
                              + ca3 * __ldg(wr + lane + 96);
                    if (lane < 15) sum = fmaf(ca4, __ldg(wr + lane + 128), sum);
#pragma unroll
                    for (int o = 16; o; o >>= 1)
                        sum += __shfl_xor_sync(0xffffffffu, sum, o);
                    if (lane == c) h[kk] += sum;
                }
            }
            float mu, rs;
            warp_ln(h, mu, rs);
            const float4* gp = reinterpret_cast<const float4*>(ctx_g)  + lane * 2;
            const float4* ep = reinterpret_cast<const float4*>(ctx_be) + lane * 2;
            const float4 g0 = __ldg(gp), g1 = __ldg(gp + 1);
            const float4 e0 = __ldg(ep), e1 = __ldg(ep + 1);
            const float gg[8] = {g0.x,g0.y,g0.z,g0.w,g1.x,g1.y,g1.z,g1.w};
            const float ee[8] = {e0.x,e0.y,e0.z,e0.w,e1.x,e1.y,e1.z,e1.w};
#pragma unroll
            for (int kk = 0; kk < 8; ++kk) {
                const float v = fmaf((h[kk] - mu) * rs, gg[kk], ee[kk]);
                ar[kk] += fmaxf(v, 0.f);
            }
        }

        // ---- store (pad -> 0), vectorized ----
        float4 o0, o1;
        if (pad) {
            o0 = make_float4(0.f, 0.f, 0.f, 0.f);
            o1 = o0;
        } else {
            o0 = make_float4(ar[0], ar[1], ar[2], ar[3]);
            o1 = make_float4(ar[4], ar[5], ar[6], ar[7]);
        }
        float4* op = reinterpret_cast<float4*>(out) + (size_t)t * 64 + lane * 2;
        op[0] = o0;
        op[1] = o1;
    }
}

} // namespace

extern "C" void kernel_launch(void* const* d_in, const int* in_sizes, int n_in,
                              void* d_out, int out_size)
{
    const int tokens = in_sizes[0];   // N*S

    poker_warp_kernel<<<NBLOCKS, 256>>>(
        (const int*)  d_in[0],   // token_ids
        (const int*)  d_in[1],   // token_streets
        (const int*)  d_in[2],   // card_ranks
        (const int*)  d_in[3],   // card_suits
        (const int*)  d_in[4],   // action_actors
        (const float*)d_in[5],   // action_legal_masks
        (const float*)d_in[6],   // context_features
        (const float*)d_in[7],   // base_emb
        (const float*)d_in[8],   // street_emb
        (const float*)d_in[9],   // rank_emb
        (const float*)d_in[10],  // suit_emb
        (const float*)d_in[11],  // actor_emb
        (const float*)d_in[12],  // atype_emb
        (const float*)d_in[13],  // legal_W
        (const float*)d_in[14],  // legal_b
        (const float*)d_in[15],  // legal_g
        (const float*)d_in[16],  // legal_beta
        (const float*)d_in[17],  // game_W
        (const float*)d_in[18],  // game_b
        (const float*)d_in[19],  // game_g
        (const float*)d_in[20],  // game_beta
        (const float*)d_in[21],  // ctx_W
        (const float*)d_in[22],  // ctx_b
        (const float*)d_in[23],  // ctx_g
        (const float*)d_in[24],  // ctx_beta
        (float*)d_out,
        tokens);
}

// round 5
// speedup vs baseline: 2.9969x; 1.3837x over previous
#include <cuda_runtime.h>
#include <cstdint>
#include <cstddef>

namespace {

constexpr int PAD_ID  = 72;     // VOCAB
constexpr int NB_MAIN = 592;    // 4 CTAs/SM * 148 SMs
constexpr int NB_CTX  = 1480;

__device__ int g_ctx_count;
__device__ int g_ctx_list[131072];

__global__ void zero_counter_kernel() { g_ctx_count = 0; }

// warp LayerNorm stats over 256 values (8 per lane)
__device__ __forceinline__ void warp_ln(const float* h, float& mu, float& rs)
{
    float s1 = 0.f, s2 = 0.f;
#pragma unroll
    for (int k = 0; k < 8; ++k) { s1 += h[k]; s2 = fmaf(h[k], h[k], s2); }
#pragma unroll
    for (int o = 16; o; o >>= 1) {
        s1 += __shfl_xor_sync(0xffffffffu, s1, o);
        s2 += __shfl_xor_sync(0xffffffffu, s2, o);
    }
    mu = s1 * (1.f / 256.f);
    float var = s2 * (1.f / 256.f) - mu * mu;
    rs = rsqrtf(var + 1e-5f);
}

// ======================= main kernel (everything except ctx MLP) =======================
__global__ __launch_bounds__(256, 4) void poker_main_kernel(
    const int*   __restrict__ token_ids,
    const int*   __restrict__ token_streets,
    const int*   __restrict__ card_ranks,
    const int*   __restrict__ card_suits,
    const int*   __restrict__ action_actors,
    const float* __restrict__ legal_masks,   // [T,16]
    const float* __restrict__ cf,            // [T,9]
    const float* __restrict__ base_emb,      // [73,256]
    const float* __restrict__ street_emb,    // [4,256]
    const float* __restrict__ rank_emb,      // [13,256]
    const float* __restrict__ suit_emb,      // [4,256]
    const float* __restrict__ actor_emb,     // [2,256]
    const float* __restrict__ atype_emb,     // [16,256]
    const float* __restrict__ legal_W,       // [256,16]
    const float* __restrict__ legal_b,
    const float* __restrict__ legal_g,
    const float* __restrict__ legal_be,
    const float* __restrict__ game_W,        // [256,5]
    const float* __restrict__ game_b,
    const float* __restrict__ game_g,
    const float* __restrict__ game_be,
    float*       __restrict__ out,           // [T,256]
    int tokens)
{
    __shared__ float4 s_W[1024];        // swizzled legal_W (16 KB)

    const int tid  = threadIdx.x;
    const int lane = tid & 31;
    const int wid  = tid >> 5;

    {
        const float4* Wg = reinterpret_cast<const float4*>(legal_W);
        for (int q = tid; q < 1024; q += 256)
            s_W[q ^ ((q >> 5) & 7)] = Wg[q];
    }
    __syncthreads();   // the ONLY block barrier

    const int gwarp  = blockIdx.x * 8 + wid;
    const int nwarp  = gridDim.x * 8;
    const int l8     = lane << 3;
    const int swbase = (lane << 5);
    const int swxor  = lane & 7;

    for (int t = gwarp; t < tokens; t += nwarp) {
        const int  raw = __ldg(token_ids + t);
        const bool pad = raw < 0;
        const int  id  = pad ? PAD_ID : raw;
        const int  st  = __ldg(token_streets + t);

        float ar[8];
        {
            const float4* bp = reinterpret_cast<const float4*>(base_emb)   + id * 64 + lane * 2;
            const float4* sp = reinterpret_cast<const float4*>(street_emb) + st * 64 + lane * 2;
            const float4 b0 = __ldg(bp), b1 = __ldg(bp + 1);
            const float4 s0 = __ldg(sp), s1 = __ldg(sp + 1);
            ar[0] = b0.x + s0.x; ar[1] = b0.y + s0.y; ar[2] = b0.z + s0.z; ar[3] = b0.w + s0.w;
            ar[4] = b1.x + s1.x; ar[5] = b1.y + s1.y; ar[6] = b1.z + s1.z; ar[7] = b1.w + s1.w;
        }

        if (id >= 4 && id < 56) {
            // ---- card token ----
            int rk = __ldg(card_ranks + t); rk = rk < 0 ? 0 : (rk > 12 ? 12 : rk);
            int su = __ldg(card_suits + t); su = su < 0 ? 0 : (su > 3  ? 3  : su);
            const float4* rp = reinterpret_cast<const float4*>(rank_emb) + rk * 64 + lane * 2;
            const float4* up = reinterpret_cast<const float4*>(suit_emb) + su * 64 + lane * 2;
            const float4 r0 = __ldg(rp), r1 = __ldg(rp + 1);
            const float4 u0 = __ldg(up), u1 = __ldg(up + 1);
            ar[0] += r0.x + u0.x; ar[1] += r0.y + u0.y; ar[2] += r0.z + u0.z; ar[3] += r0.w + u0.w;
            ar[4] += r1.x + u1.x; ar[5] += r1.y + u1.y; ar[6] += r1.z + u1.z; ar[7] += r1.w + u1.w;
        } else if (id >= 56 && id < 72) {
            // ---- action token ----
            int ac = __ldg(action_actors + t); ac = ac < 0 ? 0 : (ac > 1 ? 1 : ac);
            const float4* ap = reinterpret_cast<const float4*>(actor_emb) + ac * 64 + lane * 2;
            const float4* tp = reinterpret_cast<const float4*>(atype_emb) + (id - 56) * 64 + lane * 2;
            const float4 a0 = __ldg(ap), a1 = __ldg(ap + 1);
            const float4 y0 = __ldg(tp), y1 = __ldg(tp + 1);
            ar[0] += a0.x + y0.x; ar[1] += a0.y + y0.y; ar[2] += a0.z + y0.z; ar[3] += a0.w + y0.w;
            ar[4] += a1.x + y1.x; ar[5] += a1.y + y1.y; ar[6] += a1.z + y1.z; ar[7] += a1.w + y1.w;

            const float4* xp = reinterpret_cast<const float4*>(legal_masks) + (size_t)t * 4;
            const float4 x0 = __ldg(xp), x1 = __ldg(xp + 1), x2 = __ldg(xp + 2), x3 = __ldg(xp + 3);

            float h[8];
            {
                const float4* bbp = reinterpret_cast<const float4*>(legal_b) + lane * 2;
                const float4 hb0 = __ldg(bbp), hb1 = __ldg(bbp + 1);
                h[0]=hb0.x; h[1]=hb0.y; h[2]=hb0.z; h[3]=hb0.w;
                h[4]=hb1.x; h[5]=hb1.y; h[6]=hb1.z; h[7]=hb1.w;
            }
#pragma unroll
            for (int kk = 0; kk < 8; ++kk) {
                float4 w;
                w = s_W[swbase + (((kk << 2) | 0) ^ swxor)];
                h[kk] = fmaf(w.x, x0.x, h[kk]); h[kk] = fmaf(w.y, x0.y, h[kk]);
                h[kk] = fmaf(w.z, x0.z, h[kk]); h[kk] = fmaf(w.w, x0.w, h[kk]);
                w = s_W[swbase + (((kk << 2) | 1) ^ swxor)];
                h[kk] = fmaf(w.x, x1.x, h[kk]); h[kk] = fmaf(w.y, x1.y, h[kk]);
                h[kk] = fmaf(w.z, x1.z, h[kk]); h[kk] = fmaf(w.w, x1.w, h[kk]);
                w = s_W[swbase + (((kk << 2) | 2) ^ swxor)];
                h[kk] = fmaf(w.x, x2.x, h[kk]); h[kk] = fmaf(w.y, x2.y, h[kk]);
                h[kk] = fmaf(w.z, x2.z, h[kk]); h[kk] = fmaf(w.w, x2.w, h[kk]);
                w = s_W[swbase + (((kk << 2) | 3) ^ swxor)];
                h[kk] = fmaf(w.x, x3.x, h[kk]); h[kk] = fmaf(w.y, x3.y, h[kk]);
                h[kk] = fmaf(w.z, x3.z, h[kk]); h[kk] = fmaf(w.w, x3.w, h[kk]);
            }
            float mu, rs;
            warp_ln(h, mu, rs);
            const float4* gp = reinterpret_cast<const float4*>(legal_g)  + lane * 2;
            const float4* ep = reinterpret_cast<const float4*>(legal_be) + lane * 2;
            const float4 g0 = __ldg(gp), g1 = __ldg(gp + 1);
            const float4 e0 = __ldg(ep), e1 = __ldg(ep + 1);
            const float gg[8] = {g0.x,g0.y,g0.z,g0.w,g1.x,g1.y,g1.z,g1.w};
            const float ee[8] = {e0.x,e0.y,e0.z,e0.w,e1.x,e1.y,e1.z,e1.w};
#pragma unroll
            for (int kk = 0; kk < 8; ++kk) {
                const float v = fmaf((h[kk] - mu) * rs, gg[kk], ee[kk]);
                ar[kk] += fmaxf(v, 0.f);
            }
        } else if (id == 1) {
            // ---- ctx token: enqueue for kernel 2 ----
            if (lane == 0) {
                int slot = atomicAdd(&g_ctx_count, 1);
                g_ctx_list[slot] = t;
            }
        }

        // ---- game MLP: sequence position 0 only (256 occurrences total) ----
        if ((t & 511) == 0) {
            const int n = t >> 9;
            const float* c0 = cf + (size_t)n * 512 * 9;
            const float sb = __ldg(c0), bb = __ldg(c0 + 1), po = __ldg(c0 + 2);
            const float scale = 100.f * bb;
            const float ssg = (scale == 0.f) ? 1e-8f : scale;
            const float f3 = bb / ssg, f4 = sb / ssg;
            float h[8];
            {
                const float4* bbp = reinterpret_cast<const float4*>(game_b) + lane * 2;
                const float4 hb0 = __ldg(bbp), hb1 = __ldg(bbp + 1);
                h[0]=hb0.x; h[1]=hb0.y; h[2]=hb0.z; h[3]=hb0.w;
                h[4]=hb1.x; h[5]=hb1.y; h[6]=hb1.z; h[7]=hb1.w;
            }
#pragma unroll
            for (int kk = 0; kk < 8; ++kk) {
                const float* wr = game_W + (size_t)(l8 + kk) * 5;
                float s = h[kk];
                s = fmaf(__ldg(wr + 0), sb, s);
                s = fmaf(__ldg(wr + 1), bb, s);
                s = fmaf(__ldg(wr + 2), po, s);
                s = fmaf(__ldg(wr + 3), f3, s);
                s = fmaf(__ldg(wr + 4), f4, s);
                h[kk] = s;
            }
            float mu, rs;
            warp_ln(h, mu, rs);
            const float4* gp = reinterpret_cast<const float4*>(game_g)  + lane * 2;
            const float4* ep = reinterpret_cast<const float4*>(game_be) + lane * 2;
            const float4 g0 = __ldg(gp), g1 = __ldg(gp + 1);
            const float4 e0 = __ldg(ep), e1 = __ldg(ep + 1);
            const float gg[8] = {g0.x,g0.y,g0.z,g0.w,g1.x,g1.y,g1.z,g1.w};
            const float ee[8] = {e0.x,e0.y,e0.z,e0.w,e1.x,e1.y,e1.z,e1.w};
#pragma unroll
            for (int kk = 0; kk < 8; ++kk) {
                const float v = fmaf((h[kk] - mu) * rs, gg[kk], ee[kk]);
                ar[kk] += fmaxf(v, 0.f);
            }
        }

        // ---- store (pad -> 0), vectorized ----
        float4 o0, o1;
        if (pad) {
            o0 = make_float4(0.f, 0.f, 0.f, 0.f);
            o1 = o0;
        } else {
            o0 = make_float4(ar[0], ar[1], ar[2], ar[3]);
            o1 = make_float4(ar[4], ar[5], ar[6], ar[7]);
        }
        float4* op = reinterpret_cast<float4*>(out) + (size_t)t * 64 + lane * 2;
        op[0] = o0;
        op[1] = o1;
    }
}

// ======================= ctx kernel: one block per ctx token =======================
__global__ __launch_bounds__(256, 8) void poker_ctx_kernel(
    const float* __restrict__ cf,            // [T,9]
    const float* __restrict__ ctx_W,         // [256,143]
    const float* __restrict__ ctx_b,
    const float* __restrict__ ctx_g,
    const float* __restrict__ ctx_be,
    float*       __restrict__ out)           // [T,256]
{
    __shared__ float s_ca[160];
    __shared__ float s_red[16];
    __shared__ float s_ms[2];

    const int tid  = threadIdx.x;
    const int lane = tid & 31;
    const int wid  = tid >> 5;

    const int count = g_ctx_count;

    for (int g = blockIdx.x; g < count; g += gridDim.x) {
        __syncthreads();                    // smem reuse guard
        const int t = g_ctx_list[g];
        const int n = t >> 9;

        // ---- p[13] -> ctx_all[143] ----
        if (tid < 143) {
            const float* c0 = cf + (size_t)n * 512 * 9;
            const float* cp = cf + (size_t)t * 9;
            const float bb = __ldg(c0 + 1);
            const float scale = 100.f * bb;
            const float ssafe   = (scale == 0.f) ? 1.f : scale;
            const float bbsafe  = (bb == 0.f) ? 1.f : bb;
            const float pot     = __ldg(cp);
            const float potsafe = (pot == 0.f) ? 1.f : pot;
            const int fi = tid / 11;
            const int ps = tid - fi * 11;
            const int si = (fi < 9) ? fi : ((fi < 11) ? fi - 8 : fi - 10);
            const float num = __ldg(cp + si);
            float den = ssafe;
            if (fi == 5 || fi == 6)      den = 1.f;
            else if (fi == 9 || fi == 10) den = bbsafe;
            else if (fi >= 11)            den = potsafe;
            const float pv = num / den;
            float val;
            if (ps == 0)      val = pv;
            else if (ps <= 5) val = sinpif(pv * (float)(1 << (ps - 1)));
            else              val = cospif(pv * (float)(1 << (ps - 6)));
            s_ca[tid] = val;
        }
        __syncthreads();

        // ---- dot products: warp w owns dims [w*32, w*32+32), lane c ends with dim w*32+c ----
        const float ca0 = s_ca[lane];
        const float ca1 = s_ca[lane + 32];
        const float ca2 = s_ca[lane + 64];
        const float ca3 = s_ca[lane + 96];
        const float ca4 = (lane < 15) ? s_ca[lane + 128] : 0.f;
        float h = __ldg(ctx_b + tid);
#pragma unroll 4
        for (int c = 0; c < 32; ++c) {
            const float* wr = ctx_W + (size_t)(wid * 32 + c) * 143;
            float sum = ca0 * __ldg(wr + lane)
                      + ca1 * __ldg(wr + lane + 32)
                      + ca2 * __ldg(wr + lane + 64)
                      + ca3 * __ldg(wr + lane + 96);
            if (lane < 15) sum = fmaf(ca4, __ldg(wr + lane + 128), sum);
#pragma unroll
            for (int o = 16; o; o >>= 1)
                sum += __shfl_xor_sync(0xffffffffu, sum, o);
            if (lane == c) h += sum;
        }

        // ---- block LayerNorm over 256 dims ----
        float s1 = h, s2 = h * h;
#pragma unroll
        for (int o = 16; o; o >>= 1) {
            s1 += __shfl_xor_sync(0xffffffffu, s1, o);
            s2 += __shfl_xor_sync(0xffffffffu, s2, o);
        }
        if (lane == 0) { s_red[wid * 2] = s1; s_red[wid * 2 + 1] = s2; }
        __syncthreads();
        if (tid == 0) {
            float t1 = 0.f, t2 = 0.f;
#pragma unroll
            for (int w = 0; w < 8; ++w) { t1 += s_red[w * 2]; t2 += s_red[w * 2 + 1]; }
            const float mu  = t1 * (1.f / 256.f);
            const float var = t2 * (1.f / 256.f) - mu * mu;
            s_ms[0] = mu;
            s_ms[1] = rsqrtf(var + 1e-5f);
        }
        __syncthreads();
        const float v = fmaf((h - s_ms[0]) * s_ms[1], __ldg(ctx_g + tid), __ldg(ctx_be + tid));
        out[(size_t)t * 256 + tid] += fmaxf(v, 0.f);
    }
}

} // namespace

extern "C" void kernel_launch(void* const* d_in, const int* in_sizes, int n_in,
                              void* d_out, int out_size)
{
    const int tokens = in_sizes[0];   // N*S

    zero_counter_kernel<<<1, 1>>>();

    poker_main_kernel<<<NB_MAIN, 256>>>(
        (const int*)  d_in[0],   // token_ids
        (const int*)  d_in[1],   // token_streets
        (const int*)  d_in[2],   // card_ranks
        (const int*)  d_in[3],   // card_suits
        (const int*)  d_in[4],   // action_actors
        (const float*)d_in[5],   // action_legal_masks
        (const float*)d_in[6],   // context_features
        (const float*)d_in[7],   // base_emb
        (const float*)d_in[8],   // street_emb
        (const float*)d_in[9],   // rank_emb
        (const float*)d_in[10],  // suit_emb
        (const float*)d_in[11],  // actor_emb
        (const float*)d_in[12],  // atype_emb
        (const float*)d_in[13],  // legal_W
        (const float*)d_in[14],  // legal_b
        (const float*)d_in[15],  // legal_g
        (const float*)d_in[16],  // legal_beta
        (const float*)d_in[17],  // game_W
        (const float*)d_in[18],  // game_b
        (const float*)d_in[19],  // game_g
        (const float*)d_in[20],  // game_beta
        (float*)d_out,
        tokens);

    poker_ctx_kernel<<<NB_CTX, 256>>>(
        (const float*)d_in[6],   // context_features
        (const float*)d_in[21],  // ctx_W
        (const float*)d_in[22],  // ctx_b
        (const float*)d_in[23],  // ctx_g
        (const float*)d_in[24],  // ctx_beta
        (float*)d_out);
}